// round 14
// baseline (speedup 1.0000x reference)
#include <cuda_runtime.h>
#include <cuda_fp16.h>
#include <math.h>
#include <cstdint>

#define BB 64
#define JJ 512
#define DD 1024
#define NTOK (BB*JJ)

// Scratch (allocation-free rule: __device__ globals)
__device__ float g_valpre[NTOK];
__device__ float g_part[BB * 2 * 3];         // per-(b, d-half) W3 partials
__device__ __half g_xh[(size_t)NTOK * DD];   // 64 MB fp16 copy of x
__device__ __half g_w1h[DD * DD];            // 2 MB fp16 copy of W1

// ---------------------------------------------------------------------------
__device__ __forceinline__ uint32_t smem_u32(const void* p) {
    uint32_t a;
    asm("{ .reg .u64 t; cvta.to.shared.u64 t, %1; cvt.u32.u64 %0, t; }" : "=r"(a) : "l"(p));
    return a;
}
#define CP_ASYNC16(s, g) asm volatile("cp.async.cg.shared.global [%0], [%1], 16;" :: "r"(s), "l"(g) : "memory")
#define CP_COMMIT()      asm volatile("cp.async.commit_group;" ::: "memory")
#define CP_WAIT1()       asm volatile("cp.async.wait_group 1;" ::: "memory")
#define CP_WAIT0()       asm volatile("cp.async.wait_group 0;" ::: "memory")

__device__ __forceinline__ void ldsm_x4(uint32_t& r0, uint32_t& r1, uint32_t& r2, uint32_t& r3,
                                        uint32_t addr) {
    asm volatile("ldmatrix.sync.aligned.m8n8.x4.shared.b16 {%0,%1,%2,%3}, [%4];"
                 : "=r"(r0), "=r"(r1), "=r"(r2), "=r"(r3) : "r"(addr));
}
__device__ __forceinline__ void ldsm_x4t(uint32_t& r0, uint32_t& r1, uint32_t& r2, uint32_t& r3,
                                         uint32_t addr) {
    asm volatile("ldmatrix.sync.aligned.m8n8.x4.trans.shared.b16 {%0,%1,%2,%3}, [%4];"
                 : "=r"(r0), "=r"(r1), "=r"(r2), "=r"(r3) : "r"(addr));
}
__device__ __forceinline__ void mma16816(float* c, const uint32_t* a, uint32_t b0, uint32_t b1) {
    asm volatile(
        "mma.sync.aligned.m16n8k16.row.col.f32.f16.f16.f32 "
        "{%0,%1,%2,%3}, {%4,%5,%6,%7}, {%8,%9}, {%0,%1,%2,%3};"
        : "+f"(c[0]), "+f"(c[1]), "+f"(c[2]), "+f"(c[3])
        : "r"(a[0]), "r"(a[1]), "r"(a[2]), "r"(a[3]), "r"(b0), "r"(b1));
}

__device__ __forceinline__ float tanh_fast(float x) {
    float z = __expf(-2.f * fabsf(x));
    float t = __fdividef(1.f - z, 1.f + z);
    return copysignf(t, x);
}

// ---------------------------------------------------------------------------
// Converter: fp32 -> fp16 for x then W1, one launch (8 elems/thread).
// ---------------------------------------------------------------------------
#define XCHUNKS ((size_t)NTOK * DD / 8)          // 4,194,304
#define WCHUNKS ((size_t)DD * DD / 8)            // 131,072
__global__ __launch_bounds__(256) void k_cvt(const float* __restrict__ xsrc,
                                             const float* __restrict__ wsrc) {
    size_t c = (size_t)blockIdx.x * 256 + threadIdx.x;
    const float* src;
    __half* dst;
    size_t i;
    if (c < XCHUNKS) { src = xsrc; dst = g_xh; i = c * 8; }
    else             { src = wsrc; dst = g_w1h; i = (c - XCHUNKS) * 8; }
    float4 a = *reinterpret_cast<const float4*>(src + i);
    float4 b = *reinterpret_cast<const float4*>(src + i + 4);
    __half2 h0 = __floats2half2_rn(a.x, a.y);
    __half2 h1 = __floats2half2_rn(a.z, a.w);
    __half2 h2 = __floats2half2_rn(b.x, b.y);
    __half2 h3 = __floats2half2_rn(b.z, b.w);
    uint4 o;
    o.x = *(uint32_t*)&h0; o.y = *(uint32_t*)&h1;
    o.z = *(uint32_t*)&h2; o.w = *(uint32_t*)&h3;
    *reinterpret_cast<uint4*>(dst + i) = o;
}

// ---------------------------------------------------------------------------
// Kernel 1: raw mma.sync fp16 scoring GEMM + register-resident epilogue.
// CTA: 256 tokens x 256 e-cols/pass, 4 passes, K chunks of 64.
// 1024 threads = 32 warps (8m x 4n), warp tile 32x64 (same per-warp code as
// the verified R7 core). 3-stage pipeline, 64 chunks total. Grid = 128 CTAs.
// ---------------------------------------------------------------------------
#define M_CTA 256
#define N_TILE 256
#define K_CHUNK 64
#define NCHUNK 16
#define NPASS 4
#define TOTCHUNK (NPASS * NCHUNK)              // 64
#define A_LDH 72                               // halves (64 + 8 pad): 144B rows
#define B_LDH 264                              // halves (256 + 8 pad): 528B rows
#define A_STAGE_B (M_CTA * A_LDH * 2)          // 36864
#define B_STAGE_B (K_CHUNK * B_LDH * 2)        // 33792
#define STAGE_B   (A_STAGE_B + B_STAGE_B)      // 70656
#define NTHREAD 1024

__device__ __forceinline__ void prefetch_chunk(uint32_t dsm_u, int tokBase, int c, int tid) {
    const uint32_t base = dsm_u + (uint32_t)(c % 3) * STAGE_B;
    const int kb = (c & (NCHUNK - 1)) * K_CHUNK;
    const int eb = (c >> 4) * N_TILE;
    const __half* xh = g_xh;
    const __half* wh = g_w1h;
#pragma unroll
    for (int i = 0; i < 2; i++) {                       // A: 256 rows x 8 chunks
        int cc = tid + i * NTHREAD;
        int row = cc >> 3, q = cc & 7;
        CP_ASYNC16(base + row * (A_LDH * 2) + q * 16,
                   xh + (size_t)(tokBase + row) * DD + kb + q * 8);
    }
    const uint32_t bbase = base + A_STAGE_B;
#pragma unroll
    for (int i = 0; i < 2; i++) {                       // B: 64 rows x 32 chunks
        int cc = tid + i * NTHREAD;
        int row = cc >> 5, q = cc & 31;
        CP_ASYNC16(bbase + row * (B_LDH * 2) + q * 16,
                   wh + (size_t)(kb + row) * DD + eb + q * 8);
    }
    CP_COMMIT();
}

__global__ void __launch_bounds__(NTHREAD, 1)
k_score_mma(const float* __restrict__ b1, const float* __restrict__ W2)
{
    extern __shared__ __align__(16) char dsm[];            // 3 stages
    __shared__ __align__(8) float s_b1[DD];
    __shared__ __align__(8) float s_w2[DD];
    __shared__ float s_val[4][M_CTA];

    const int tid = threadIdx.x;
    const int wid = tid >> 5;
    const int lane = tid & 31;
    const int warp_m = wid >> 2;          // 0..7  (32 tokens each)
    const int warp_n = wid & 3;           // 0..3  (64 cols each)
    const int tokBase = blockIdx.x * M_CTA;

    const uint32_t dsm_u = smem_u32(dsm);

    for (int i = tid; i < DD; i += NTHREAD) { s_b1[i] = b1[i]; s_w2[i] = W2[i]; }

    const int l15 = lane & 15;
    const int lhi = lane >> 4;
    const uint32_t a_lane_base = (uint32_t)((warp_m * 32 + l15) * (A_LDH * 2) + lhi * 16);
    const uint32_t b_lane_base = (uint32_t)(A_STAGE_B + l15 * (B_LDH * 2)
                                            + warp_n * 128 + lhi * 16);

    float rowAcc[4] = {0.f, 0.f, 0.f, 0.f};

    prefetch_chunk(dsm_u, tokBase, 0, tid);
    prefetch_chunk(dsm_u, tokBase, 1, tid);

    for (int nt = 0; nt < NPASS; nt++) {
        const int eb = nt * N_TILE;

        float acc[2][8][4];
#pragma unroll
        for (int fm = 0; fm < 2; fm++)
#pragma unroll
            for (int fn = 0; fn < 8; fn++)
#pragma unroll
                for (int e = 0; e < 4; e++) acc[fm][fn][e] = 0.f;

        for (int kc = 0; kc < NCHUNK; kc++) {
            const int c = nt * NCHUNK + kc;
            if (c == TOTCHUNK - 1) { CP_WAIT0(); } else { CP_WAIT1(); }
            __syncthreads();
            if (c + 2 < TOTCHUNK) prefetch_chunk(dsm_u, tokBase, c + 2, tid);

            const uint32_t stg = dsm_u + (uint32_t)(c % 3) * STAGE_B;

#pragma unroll
            for (int kk = 0; kk < 4; kk++) {
                uint32_t a0[4], a1[4];
                ldsm_x4(a0[0], a0[1], a0[2], a0[3],
                        stg + a_lane_base + kk * 32);
                ldsm_x4(a1[0], a1[1], a1[2], a1[3],
                        stg + a_lane_base + 16 * (A_LDH * 2) + kk * 32);
#pragma unroll
                for (int nb = 0; nb < 4; nb++) {
                    uint32_t b0, b1r, b2, b3;
                    ldsm_x4t(b0, b1r, b2, b3,
                             stg + b_lane_base + kk * 16 * (B_LDH * 2) + nb * 32);
                    mma16816(acc[0][nb * 2 + 0], a0, b0, b1r);
                    mma16816(acc[0][nb * 2 + 1], a0, b2, b3);
                    mma16816(acc[1][nb * 2 + 0], a1, b0, b1r);
                    mma16816(acc[1][nb * 2 + 1], a1, b2, b3);
                }
            }
        }

#pragma unroll
        for (int fn = 0; fn < 8; fn++) {
            const int col = eb + warp_n * 64 + fn * 8 + (lane & 3) * 2;
            const float2 bv = *reinterpret_cast<const float2*>(&s_b1[col]);
            const float2 wv = *reinterpret_cast<const float2*>(&s_w2[col]);
#pragma unroll
            for (int fm = 0; fm < 2; fm++) {
                const float* a4 = acc[fm][fn];
                rowAcc[fm * 2 + 0] += tanh_fast(a4[0] + bv.x) * wv.x
                                    + tanh_fast(a4[1] + bv.y) * wv.y;
                rowAcc[fm * 2 + 1] += tanh_fast(a4[2] + bv.x) * wv.x
                                    + tanh_fast(a4[3] + bv.y) * wv.y;
            }
        }
    }

#pragma unroll
    for (int i = 0; i < 4; i++) {
        rowAcc[i] += __shfl_xor_sync(0xffffffffu, rowAcc[i], 1);
        rowAcc[i] += __shfl_xor_sync(0xffffffffu, rowAcc[i], 2);
    }
    if ((lane & 3) == 0) {
        const int r = lane >> 2;
        const int base = warp_m * 32;
        s_val[warp_n][base + r]      = rowAcc[0];
        s_val[warp_n][base + r + 8]  = rowAcc[1];
        s_val[warp_n][base + r + 16] = rowAcc[2];
        s_val[warp_n][base + r + 24] = rowAcc[3];
    }
    __syncthreads();
    if (tid < M_CTA)
        g_valpre[tokBase + tid] =
            s_val[0][tid] + s_val[1][tid] + s_val[2][tid] + s_val[3][tid];
}

// ---------------------------------------------------------------------------
// Kernel 2: fused finalize + pool (fp16 x) + W3 partials.  (R10 config)
// Grid (2, 64); block = 512-wide d-chunk, each thread 2 cols via __half2.
// ---------------------------------------------------------------------------
__global__ __launch_bounds__(256) void k_finpool(const float* __restrict__ mask,
                                                 const float* __restrict__ b2,
                                                 const float* __restrict__ W3,
                                                 float* __restrict__ out_att)
{
    __shared__ float sa[JJ];
    __shared__ float sred[8];
    __shared__ float sred3[3][8];
    const int b = blockIdx.y;
    const int tid = threadIdx.x;
    const float b2v = b2[0];

    float v[2];
#pragma unroll
    for (int i = 0; i < 2; i++) {
        int j = tid + i * 256;
        float t = g_valpre[b * JJ + j];
        t = 1.f / (1.f + __expf(-(t + b2v)));
        v[i] = t * mask[b * JJ + j];
    }
    float s = v[0] + v[1];
#pragma unroll
    for (int o = 16; o; o >>= 1) s += __shfl_xor_sync(0xffffffffu, s, o);
    if ((tid & 31) == 0) sred[tid >> 5] = s;
    __syncthreads();
    if (tid < 8) {
        float t = sred[tid];
#pragma unroll
        for (int o = 4; o; o >>= 1) t += __shfl_xor_sync(0xffu, t, o);
        if (tid == 0) sred[0] = t;
    }
    __syncthreads();
    const float inv = 1.f / sred[0];

#pragma unroll
    for (int i = 0; i < 2; i++) {
        int j = tid + i * 256;
        float a = v[i] * inv;
        sa[j] = a;
        if (blockIdx.x == 0) out_att[b * JJ + j] = a;
    }
    __syncthreads();

    const int d0 = blockIdx.x * 512 + tid * 2;
    float accx = 0.f, accy = 0.f;
    const __half2* xb2 = reinterpret_cast<const __half2*>(
        g_xh + (size_t)b * JJ * DD + d0);
#pragma unroll 8
    for (int j = 0; j < JJ; j++) {
        float2 f = __half22float2(xb2[(size_t)j * (DD / 2)]);
        float a = sa[j];
        accx += f.x * a;
        accy += f.y * a;
    }

    float p0 = accx * W3[d0 * 3 + 0] + accy * W3[(d0 + 1) * 3 + 0];
    float p1 = accx * W3[d0 * 3 + 1] + accy * W3[(d0 + 1) * 3 + 1];
    float p2 = accx * W3[d0 * 3 + 2] + accy * W3[(d0 + 1) * 3 + 2];
#pragma unroll
    for (int o = 16; o; o >>= 1) {
        p0 += __shfl_xor_sync(0xffffffffu, p0, o);
        p1 += __shfl_xor_sync(0xffffffffu, p1, o);
        p2 += __shfl_xor_sync(0xffffffffu, p2, o);
    }
    if ((tid & 31) == 0) {
        sred3[0][tid >> 5] = p0; sred3[1][tid >> 5] = p1; sred3[2][tid >> 5] = p2;
    }
    __syncthreads();
    if (tid < 3) {
        float t = 0.f;
#pragma unroll
        for (int w = 0; w < 8; w++) t += sred3[tid][w];
        g_part[(b * 2 + blockIdx.x) * 3 + tid] = t;
    }
}

// ---------------------------------------------------------------------------
// Kernel 3: tiny final sum of W3 partials.
// ---------------------------------------------------------------------------
__global__ __launch_bounds__(192) void k_out2(const float* __restrict__ b3,
                                              float* __restrict__ out)
{
    const int t = threadIdx.x;     // 192 = 64 b x 3 o
    const int b = t / 3, o = t % 3;
    float s = b3[o];
#pragma unroll
    for (int c = 0; c < 2; c++) s += g_part[(b * 2 + c) * 3 + o];
    out[b * 3 + o] = s;
}

// ---------------------------------------------------------------------------
extern "C" void kernel_launch(void* const* d_in, const int* in_sizes, int n_in,
                              void* d_out, int out_size)
{
    const float* x    = (const float*)d_in[0];
    const float* mask = (const float*)d_in[1];
    const float* W1   = (const float*)d_in[2];
    const float* b1   = (const float*)d_in[3];
    const float* W2   = (const float*)d_in[4];
    const float* b2   = (const float*)d_in[5];
    const float* W3   = (const float*)d_in[6];
    const float* b3   = (const float*)d_in[7];
    float* out = (float*)d_out;

    float* out_val = out;            // [64,3]
    float* out_att = out + BB * 3;   // [64,512,1]

    const int smem_bytes = 3 * STAGE_B;   // 211968
    cudaFuncSetAttribute(k_score_mma, cudaFuncAttributeMaxDynamicSharedMemorySize, smem_bytes);

    k_cvt<<<(int)((XCHUNKS + WCHUNKS) / 256), 256>>>(x, W1);
    k_score_mma<<<NTOK / M_CTA, NTHREAD, smem_bytes>>>(b1, W2);
    dim3 gfp(2, BB);
    k_finpool<<<gfp, 256>>>(mask, b2, W3, out_att);
    k_out2<<<1, 192>>>(b3, out_val);
}

// round 15
// speedup vs baseline: 3.0695x; 3.0695x over previous
#include <cuda_runtime.h>
#include <cuda_fp16.h>
#include <math.h>
#include <cstdint>

#define BB 64
#define JJ 512
#define DD 1024
#define NTOK (BB*JJ)

// Scratch (allocation-free rule: __device__ globals)
__device__ float g_valpre[NTOK];
__device__ float g_part[BB * 2 * 3];         // per-(b, d-half) W3 partials
__device__ __half g_xh[(size_t)NTOK * DD];   // 64 MB fp16 copy of x
__device__ __half g_w1h[DD * DD];            // 2 MB fp16 copy of W1

// ---------------------------------------------------------------------------
__device__ __forceinline__ uint32_t smem_u32(const void* p) {
    uint32_t a;
    asm("{ .reg .u64 t; cvta.to.shared.u64 t, %1; cvt.u32.u64 %0, t; }" : "=r"(a) : "l"(p));
    return a;
}
#define CP_ASYNC16(s, g) asm volatile("cp.async.cg.shared.global [%0], [%1], 16;" :: "r"(s), "l"(g) : "memory")
#define CP_COMMIT()      asm volatile("cp.async.commit_group;" ::: "memory")
#define CP_WAIT2()       asm volatile("cp.async.wait_group 2;" ::: "memory")
#define CP_WAIT1()       asm volatile("cp.async.wait_group 1;" ::: "memory")
#define CP_WAIT0()       asm volatile("cp.async.wait_group 0;" ::: "memory")

__device__ __forceinline__ void ldsm_x4(uint32_t& r0, uint32_t& r1, uint32_t& r2, uint32_t& r3,
                                        uint32_t addr) {
    asm volatile("ldmatrix.sync.aligned.m8n8.x4.shared.b16 {%0,%1,%2,%3}, [%4];"
                 : "=r"(r0), "=r"(r1), "=r"(r2), "=r"(r3) : "r"(addr));
}
__device__ __forceinline__ void ldsm_x4t(uint32_t& r0, uint32_t& r1, uint32_t& r2, uint32_t& r3,
                                         uint32_t addr) {
    asm volatile("ldmatrix.sync.aligned.m8n8.x4.trans.shared.b16 {%0,%1,%2,%3}, [%4];"
                 : "=r"(r0), "=r"(r1), "=r"(r2), "=r"(r3) : "r"(addr));
}
__device__ __forceinline__ void mma16816(float* c, const uint32_t* a, uint32_t b0, uint32_t b1) {
    asm volatile(
        "mma.sync.aligned.m16n8k16.row.col.f32.f16.f16.f32 "
        "{%0,%1,%2,%3}, {%4,%5,%6,%7}, {%8,%9}, {%0,%1,%2,%3};"
        : "+f"(c[0]), "+f"(c[1]), "+f"(c[2]), "+f"(c[3])
        : "r"(a[0]), "r"(a[1]), "r"(a[2]), "r"(a[3]), "r"(b0), "r"(b1));
}

__device__ __forceinline__ float tanh_fast(float x) {
    float z = __expf(-2.f * fabsf(x));
    float t = __fdividef(1.f - z, 1.f + z);
    return copysignf(t, x);
}

// ---------------------------------------------------------------------------
// Converter: fp32 -> fp16 for x then W1, one launch (8 elems/thread).
// ---------------------------------------------------------------------------
#define XCHUNKS ((size_t)NTOK * DD / 8)          // 4,194,304
#define WCHUNKS ((size_t)DD * DD / 8)            // 131,072
__global__ __launch_bounds__(256) void k_cvt(const float* __restrict__ xsrc,
                                             const float* __restrict__ wsrc) {
    size_t c = (size_t)blockIdx.x * 256 + threadIdx.x;
    const float* src;
    __half* dst;
    size_t i;
    if (c < XCHUNKS) { src = xsrc; dst = g_xh; i = c * 8; }
    else             { src = wsrc; dst = g_w1h; i = (c - XCHUNKS) * 8; }
    float4 a = *reinterpret_cast<const float4*>(src + i);
    float4 b = *reinterpret_cast<const float4*>(src + i + 4);
    __half2 h0 = __floats2half2_rn(a.x, a.y);
    __half2 h1 = __floats2half2_rn(a.z, a.w);
    __half2 h2 = __floats2half2_rn(b.x, b.y);
    __half2 h3 = __floats2half2_rn(b.z, b.w);
    uint4 o;
    o.x = *(uint32_t*)&h0; o.y = *(uint32_t*)&h1;
    o.z = *(uint32_t*)&h2; o.w = *(uint32_t*)&h3;
    *reinterpret_cast<uint4*>(dst + i) = o;
}

// ---------------------------------------------------------------------------
// Kernel 1: raw mma.sync fp16 scoring GEMM + register-resident epilogue.
// CTA: 256 tokens x 128 e-cols/pass, 8 passes, K chunks of 64.
// 512 threads, 16 warps = 8m x 2n (the verified R7/R10 core).
// 4-stage cp.async pipeline, prefetch distance 3. Grid = 128 CTAs.
// ---------------------------------------------------------------------------
#define M_CTA 256
#define N_TILE 128
#define K_CHUNK 64
#define NCHUNK 16
#define NPASS 8
#define TOTCHUNK (NPASS * NCHUNK)              // 128
#define NSTAGE 4
#define A_LDH 72                               // halves (64 + 8 pad): 144B rows
#define B_LDH 136                              // halves (128 + 8 pad): 272B rows
#define A_STAGE_B (M_CTA * A_LDH * 2)          // 36864
#define B_STAGE_B (K_CHUNK * B_LDH * 2)        // 17408
#define STAGE_B   (A_STAGE_B + B_STAGE_B)      // 54272
#define NWARP 16
#define NTHREAD 512

__device__ __forceinline__ void prefetch_chunk(uint32_t dsm_u, int tokBase, int c, int tid) {
    const uint32_t base = dsm_u + (uint32_t)(c % NSTAGE) * STAGE_B;
    const int kb = (c & (NCHUNK - 1)) * K_CHUNK;
    const int eb = (c >> 4) * N_TILE;
    const __half* xh = g_xh;
    const __half* wh = g_w1h;
#pragma unroll
    for (int i = 0; i < 4; i++) {                       // A: 256 rows x 8 chunks
        int cc = tid + i * NTHREAD;
        int row = cc >> 3, q = cc & 7;
        CP_ASYNC16(base + row * (A_LDH * 2) + q * 16,
                   xh + (size_t)(tokBase + row) * DD + kb + q * 8);
    }
    const uint32_t bbase = base + A_STAGE_B;
#pragma unroll
    for (int i = 0; i < 2; i++) {                       // B: 64 rows x 16 chunks
        int cc = tid + i * NTHREAD;
        int row = cc >> 4, q = cc & 15;
        CP_ASYNC16(bbase + row * (B_LDH * 2) + q * 16,
                   wh + (size_t)(kb + row) * DD + eb + q * 8);
    }
    CP_COMMIT();
}

__global__ void __launch_bounds__(NTHREAD, 1)
k_score_mma(const float* __restrict__ b1, const float* __restrict__ W2)
{
    extern __shared__ __align__(16) char dsm[];            // 4 stages
    __shared__ __align__(8) float s_b1[DD];
    __shared__ __align__(8) float s_w2[DD];
    __shared__ float s_val[2][M_CTA];

    const int tid = threadIdx.x;
    const int wid = tid >> 5;
    const int lane = tid & 31;
    const int warp_m = wid >> 1;          // 0..7  (32 tokens each)
    const int warp_n = wid & 1;           // 0..1  (64 cols each)
    const int tokBase = blockIdx.x * M_CTA;

    const uint32_t dsm_u = smem_u32(dsm);

    for (int i = tid; i < DD; i += NTHREAD) { s_b1[i] = b1[i]; s_w2[i] = W2[i]; }

    const int l15 = lane & 15;
    const int lhi = lane >> 4;
    const uint32_t a_lane_base = (uint32_t)((warp_m * 32 + l15) * (A_LDH * 2) + lhi * 16);
    const uint32_t b_lane_base = (uint32_t)(A_STAGE_B + l15 * (B_LDH * 2)
                                            + warp_n * 128 + lhi * 16);

    float rowAcc[4] = {0.f, 0.f, 0.f, 0.f};

    // prologue: chunks 0, 1, 2
    prefetch_chunk(dsm_u, tokBase, 0, tid);
    prefetch_chunk(dsm_u, tokBase, 1, tid);
    prefetch_chunk(dsm_u, tokBase, 2, tid);

    for (int nt = 0; nt < NPASS; nt++) {
        const int eb = nt * N_TILE;

        float acc[2][8][4];
#pragma unroll
        for (int fm = 0; fm < 2; fm++)
#pragma unroll
            for (int fn = 0; fn < 8; fn++)
#pragma unroll
                for (int e = 0; e < 4; e++) acc[fm][fn][e] = 0.f;

        for (int kc = 0; kc < NCHUNK; kc++) {
            const int c = nt * NCHUNK + kc;
            // wait ladder: ensure chunk c's group is complete
            if (c + 2 < TOTCHUNK)      { CP_WAIT2(); }
            else if (c + 1 < TOTCHUNK) { CP_WAIT1(); }
            else                       { CP_WAIT0(); }
            __syncthreads();
            if (c + 3 < TOTCHUNK) prefetch_chunk(dsm_u, tokBase, c + 3, tid);

            const uint32_t stg = dsm_u + (uint32_t)(c % NSTAGE) * STAGE_B;

#pragma unroll
            for (int kk = 0; kk < 4; kk++) {
                uint32_t a0[4], a1[4];
                ldsm_x4(a0[0], a0[1], a0[2], a0[3],
                        stg + a_lane_base + kk * 32);
                ldsm_x4(a1[0], a1[1], a1[2], a1[3],
                        stg + a_lane_base + 16 * (A_LDH * 2) + kk * 32);
#pragma unroll
                for (int nb = 0; nb < 4; nb++) {
                    uint32_t b0, b1r, b2, b3;
                    ldsm_x4t(b0, b1r, b2, b3,
                             stg + b_lane_base + kk * 16 * (B_LDH * 2) + nb * 32);
                    mma16816(acc[0][nb * 2 + 0], a0, b0, b1r);
                    mma16816(acc[0][nb * 2 + 1], a0, b2, b3);
                    mma16816(acc[1][nb * 2 + 0], a1, b0, b1r);
                    mma16816(acc[1][nb * 2 + 1], a1, b2, b3);
                }
            }
        }

#pragma unroll
        for (int fn = 0; fn < 8; fn++) {
            const int col = eb + warp_n * 64 + fn * 8 + (lane & 3) * 2;
            const float2 bv = *reinterpret_cast<const float2*>(&s_b1[col]);
            const float2 wv = *reinterpret_cast<const float2*>(&s_w2[col]);
#pragma unroll
            for (int fm = 0; fm < 2; fm++) {
                const float* a4 = acc[fm][fn];
                rowAcc[fm * 2 + 0] += tanh_fast(a4[0] + bv.x) * wv.x
                                    + tanh_fast(a4[1] + bv.y) * wv.y;
                rowAcc[fm * 2 + 1] += tanh_fast(a4[2] + bv.x) * wv.x
                                    + tanh_fast(a4[3] + bv.y) * wv.y;
            }
        }
    }

#pragma unroll
    for (int i = 0; i < 4; i++) {
        rowAcc[i] += __shfl_xor_sync(0xffffffffu, rowAcc[i], 1);
        rowAcc[i] += __shfl_xor_sync(0xffffffffu, rowAcc[i], 2);
    }
    if ((lane & 3) == 0) {
        const int r = lane >> 2;
        const int base = warp_m * 32;
        s_val[warp_n][base + r]      = rowAcc[0];
        s_val[warp_n][base + r + 8]  = rowAcc[1];
        s_val[warp_n][base + r + 16] = rowAcc[2];
        s_val[warp_n][base + r + 24] = rowAcc[3];
    }
    __syncthreads();
    for (int t = tid; t < M_CTA; t += NTHREAD)
        g_valpre[tokBase + t] = s_val[0][t] + s_val[1][t];
}

// ---------------------------------------------------------------------------
// Kernel 2: fused finalize + pool (fp16 x) + W3 partials.  (R10 config)
// Grid (2, 64); block = 512-wide d-chunk, each thread 2 cols via __half2.
// ---------------------------------------------------------------------------
__global__ __launch_bounds__(256) void k_finpool(const float* __restrict__ mask,
                                                 const float* __restrict__ b2,
                                                 const float* __restrict__ W3,
                                                 float* __restrict__ out_att)
{
    __shared__ float sa[JJ];
    __shared__ float sred[8];
    __shared__ float sred3[3][8];
    const int b = blockIdx.y;
    const int tid = threadIdx.x;
    const float b2v = b2[0];

    float v[2];
#pragma unroll
    for (int i = 0; i < 2; i++) {
        int j = tid + i * 256;
        float t = g_valpre[b * JJ + j];
        t = 1.f / (1.f + __expf(-(t + b2v)));
        v[i] = t * mask[b * JJ + j];
    }
    float s = v[0] + v[1];
#pragma unroll
    for (int o = 16; o; o >>= 1) s += __shfl_xor_sync(0xffffffffu, s, o);
    if ((tid & 31) == 0) sred[tid >> 5] = s;
    __syncthreads();
    if (tid < 8) {
        float t = sred[tid];
#pragma unroll
        for (int o = 4; o; o >>= 1) t += __shfl_xor_sync(0xffu, t, o);
        if (tid == 0) sred[0] = t;
    }
    __syncthreads();
    const float inv = 1.f / sred[0];

#pragma unroll
    for (int i = 0; i < 2; i++) {
        int j = tid + i * 256;
        float a = v[i] * inv;
        sa[j] = a;
        if (blockIdx.x == 0) out_att[b * JJ + j] = a;
    }
    __syncthreads();

    const int d0 = blockIdx.x * 512 + tid * 2;
    float accx = 0.f, accy = 0.f;
    const __half2* xb2 = reinterpret_cast<const __half2*>(
        g_xh + (size_t)b * JJ * DD + d0);
#pragma unroll 8
    for (int j = 0; j < JJ; j++) {
        float2 f = __half22float2(xb2[(size_t)j * (DD / 2)]);
        float a = sa[j];
        accx += f.x * a;
        accy += f.y * a;
    }

    float p0 = accx * W3[d0 * 3 + 0] + accy * W3[(d0 + 1) * 3 + 0];
    float p1 = accx * W3[d0 * 3 + 1] + accy * W3[(d0 + 1) * 3 + 1];
    float p2 = accx * W3[d0 * 3 + 2] + accy * W3[(d0 + 1) * 3 + 2];
#pragma unroll
    for (int o = 16; o; o >>= 1) {
        p0 += __shfl_xor_sync(0xffffffffu, p0, o);
        p1 += __shfl_xor_sync(0xffffffffu, p1, o);
        p2 += __shfl_xor_sync(0xffffffffu, p2, o);
    }
    if ((tid & 31) == 0) {
        sred3[0][tid >> 5] = p0; sred3[1][tid >> 5] = p1; sred3[2][tid >> 5] = p2;
    }
    __syncthreads();
    if (tid < 3) {
        float t = 0.f;
#pragma unroll
        for (int w = 0; w < 8; w++) t += sred3[tid][w];
        g_part[(b * 2 + blockIdx.x) * 3 + tid] = t;
    }
}

// ---------------------------------------------------------------------------
// Kernel 3: tiny final sum of W3 partials.
// ---------------------------------------------------------------------------
__global__ __launch_bounds__(192) void k_out2(const float* __restrict__ b3,
                                              float* __restrict__ out)
{
    const int t = threadIdx.x;     // 192 = 64 b x 3 o
    const int b = t / 3, o = t % 3;
    float s = b3[o];
#pragma unroll
    for (int c = 0; c < 2; c++) s += g_part[(b * 2 + c) * 3 + o];
    out[b * 3 + o] = s;
}

// ---------------------------------------------------------------------------
extern "C" void kernel_launch(void* const* d_in, const int* in_sizes, int n_in,
                              void* d_out, int out_size)
{
    const float* x    = (const float*)d_in[0];
    const float* mask = (const float*)d_in[1];
    const float* W1   = (const float*)d_in[2];
    const float* b1   = (const float*)d_in[3];
    const float* W2   = (const float*)d_in[4];
    const float* b2   = (const float*)d_in[5];
    const float* W3   = (const float*)d_in[6];
    const float* b3   = (const float*)d_in[7];
    float* out = (float*)d_out;

    float* out_val = out;            // [64,3]
    float* out_att = out + BB * 3;   // [64,512,1]

    const int smem_bytes = NSTAGE * STAGE_B;   // 217088
    cudaFuncSetAttribute(k_score_mma, cudaFuncAttributeMaxDynamicSharedMemorySize, smem_bytes);

    k_cvt<<<(int)((XCHUNKS + WCHUNKS) / 256), 256>>>(x, W1);
    k_score_mma<<<NTOK / M_CTA, NTHREAD, smem_bytes>>>(b1, W2);
    dim3 gfp(2, BB);
    k_finpool<<<gfp, 256>>>(mask, b2, W3, out_att);
    k_out2<<<1, 192>>>(b3, out_val);
}